// round 7
// baseline (speedup 1.0000x reference)
#include <cuda_runtime.h>
#include <math.h>

#define F_IN   32
#define DDIM   128
#define HEADS  4
#define HD     512               // HEADS * DDIM
#define RNN3   384
#define NSCAN  146               // scan blocks (bids 1..146)
#define NBLK   (NSCAN + 1)       // + bid 0 = producer/finale
#define NTHR   512
#define LCAP   2304              // >= worst-case hits in one stripe

// Persistent scratch (allocation-free rule). Finale resets all consumed state
// so graph replays stay correct (launches are stream-serialized).
__device__ float g_num[HD];
__device__ float g_den[HEADS];
__device__ int   g_scanned;
__device__ volatile int g_xr0_flag;
__device__ float g_xr0[HD];

__global__ void __launch_bounds__(NTHR, 1) fused_stgat(
    const float* __restrict__ nf,     const float* __restrict__ hidden,
    const float* __restrict__ W_enc,  const float* __restrict__ b_enc,
    const float* __restrict__ W_l,    const float* __restrict__ b_l,
    const float* __restrict__ W_r,    const float* __restrict__ b_r,
    const float* __restrict__ att,    const float* __restrict__ gat_bias,
    const float* __restrict__ W_ih,   const float* __restrict__ W_hh,
    const float* __restrict__ b_ih,   const float* __restrict__ b_hh,
    const int*   __restrict__ ei,     int E,
    float* __restrict__ out)
{
    __shared__ __align__(16) float hs[DDIM];
    __shared__ __align__(16) float part[4 * HD];   // 4-way K-split partials
    __shared__ float red[16];
    __shared__ float psh[HEADS];

    const int t = threadIdx.x, b = blockIdx.x;
    const int warp = t >> 5, lane = t & 31;
    const int grp = t >> 7, q = t & 127;   // 4 K-groups x 128 outputs

    const int n4 = E >> 2;

    if (b == 0) {
        // ================= Producer + finale block =================
        __shared__ float gh[RNN3];
        __shared__ float gat[DDIM];
        __shared__ float gi[RNN3];
        __shared__ float hid[DDIM];

        // --- h0 = relu(nf[0]@W_enc + b_enc) (4-way K split over 512 thr)
        {
            float a = 0.f;
            #pragma unroll
            for (int k = 0; k < 8; k++)
                a += nf[grp*8 + k] * W_enc[(grp*8 + k)*DDIM + q];
            part[grp*DDIM + q] = a;
        }
        __syncthreads();
        if (t < DDIM)
            hs[t] = fmaxf(b_enc[t] + part[t] + part[DDIM+t] + part[2*DDIM+t] + part[3*DDIM+t], 0.f);
        __syncthreads();
        // --- xr0 = h0 @ W_r + b_r  (float4, 4-way K split)
        {
            float4 a = make_float4(0.f, 0.f, 0.f, 0.f);
            const float* Wb = W_r + (size_t)(grp*32)*HD + 4*q;
            #pragma unroll
            for (int j = 0; j < 32; j++) {
                const float4 wv = *(const float4*)(Wb + (size_t)j*HD);
                const float hv = hs[grp*32 + j];
                a.x += hv*wv.x; a.y += hv*wv.y; a.z += hv*wv.z; a.w += hv*wv.w;
            }
            *(float4*)(part + grp*HD + 4*q) = a;
        }
        __syncthreads();
        g_xr0[t] = b_r[t] + part[t] + part[HD+t] + part[2*HD+t] + part[3*HD+t];
        __threadfence();
        __syncthreads();
        if (t == 0) g_xr0_flag = 1;

        // --- gh = hidden @ W_hh.T + b_hh into SMEM (overlaps with scanners)
        if (t < DDIM) hid[t] = hidden[t];
        __syncthreads();
        {
            const int base = warp * 24;
            const float x0 = hid[lane*4+0], x1 = hid[lane*4+1];
            const float x2 = hid[lane*4+2], x3 = hid[lane*4+3];
            for (int i = 0; i < 24; i += 4) {
                float acc[4];
                #pragma unroll
                for (int j = 0; j < 4; j++) {
                    const float4 wv = *(const float4*)(W_hh + (size_t)(base+i+j)*DDIM + lane*4);
                    acc[j] = wv.x*x0 + wv.y*x1 + wv.z*x2 + wv.w*x3;
                }
                #pragma unroll
                for (int off = 16; off; off >>= 1)
                    #pragma unroll
                    for (int j = 0; j < 4; j++)
                        acc[j] += __shfl_xor_sync(0xffffffffu, acc[j], off);
                if (lane == 0)
                    #pragma unroll
                    for (int j = 0; j < 4; j++)
                        gh[base+i+j] = acc[j] + b_hh[base+i+j];
            }
        }

        // --- wait until every scan block has published its contributions
        if (t == 0) {
            volatile int* sc = &g_scanned;
            while (*sc < NSCAN) {}
        }
        __syncthreads();
        __threadfence();   // acquire scanners' L2 atomic writes

        if (t < DDIM) {
            float s = 0.f;
            #pragma unroll
            for (int h = 0; h < HEADS; h++)
                s += g_num[h*DDIM + t] / fmaxf(g_den[h], 1e-16f);
            gat[t] = 0.25f * s + gat_bias[t];
        }
        __syncthreads();

        // reset persistent state for next replay
        g_num[t] = 0.f;
        if (t < HEADS) g_den[t] = 0.f;
        if (t == 0) { g_scanned = 0; g_xr0_flag = 0; }

        // gi = gat @ W_ih.T + b_ih : 16 warps x 24 rows, float4
        {
            const int base = warp * 24;
            const float x0 = gat[lane*4+0], x1 = gat[lane*4+1];
            const float x2 = gat[lane*4+2], x3 = gat[lane*4+3];
            for (int i = 0; i < 24; i += 4) {
                float acc[4];
                #pragma unroll
                for (int j = 0; j < 4; j++) {
                    const float4 wv = *(const float4*)(W_ih + (size_t)(base+i+j)*DDIM + lane*4);
                    acc[j] = wv.x*x0 + wv.y*x1 + wv.z*x2 + wv.w*x3;
                }
                #pragma unroll
                for (int off = 16; off; off >>= 1)
                    #pragma unroll
                    for (int j = 0; j < 4; j++)
                        acc[j] += __shfl_xor_sync(0xffffffffu, acc[j], off);
                if (lane == 0)
                    #pragma unroll
                    for (int j = 0; j < 4; j++)
                        gi[base+i+j] = acc[j] + b_ih[base+i+j];
            }
        }
        __syncthreads();

        if (t < DDIM) {
            float r  = 1.f / (1.f + expf(-(gi[t]        + gh[t])));
            float z  = 1.f / (1.f + expf(-(gi[DDIM+t]   + gh[DDIM+t])));
            float ng = tanhf(gi[2*DDIM+t] + r * gh[2*DDIM+t]);
            out[t] = (1.f - z) * ng + z * hid[t];
        }
        return;
    }

    // ================= Scan blocks (bids 1..NSCAN) =================
    __shared__ int ls[LCAP];
    __shared__ int lcnt;
    if (t == 0) lcnt = 0;
    __syncthreads();

    const int idx = b - 1;
    const int chunk = (n4 + NSCAN - 1) / NSCAN;
    const int lo = idx * chunk;
    const int hi = min(n4, lo + chunk);
    const int4* dst4 = (const int4*)(ei + E);
    for (int i = lo + t; i < hi; i += NTHR) {
        int4 v = dst4[i];
        if (v.x == 0) ls[atomicAdd(&lcnt, 1)] = ei[4*i+0];
        if (v.y == 0) ls[atomicAdd(&lcnt, 1)] = ei[4*i+1];
        if (v.z == 0) ls[atomicAdd(&lcnt, 1)] = ei[4*i+2];
        if (v.w == 0) ls[atomicAdd(&lcnt, 1)] = ei[4*i+3];
    }
    if (idx == 0) {
        for (int i = 4*n4 + t; i < E; i += NTHR)       // tail if E % 4
            if (ei[E + i] == 0) ls[atomicAdd(&lcnt, 1)] = ei[i];
        if (t == 0) ls[atomicAdd(&lcnt, 1)] = 0;       // self-loop node 0
    }
    __syncthreads();

    const int cnt = min(lcnt, LCAP);
    if (cnt > 0) {
        bool got = false;
        float myxr0 = 0.f;
        float accN = 0.f;   // per-thread Σ_e p_e * xl_e[t]
        float accD = 0.f;   // valid on t < HEADS: Σ_e p_e[head=t]

        for (int e = 0; e < cnt; e++) {
            const int s = ls[e];
            {   // hs partials
                const float* row = nf + (size_t)s * F_IN;
                float a = 0.f;
                #pragma unroll
                for (int k = 0; k < 8; k++)
                    a += row[grp*8 + k] * W_enc[(grp*8 + k)*DDIM + q];
                part[grp*DDIM + q] = a;
            }
            __syncthreads();
            if (t < DDIM)
                hs[t] = fmaxf(b_enc[t] + part[t] + part[DDIM+t] + part[2*DDIM+t] + part[3*DDIM+t], 0.f);
            __syncthreads();

            {   // xl: float4 4-way K split
                float4 a = make_float4(0.f, 0.f, 0.f, 0.f);
                const float* Wb = W_l + (size_t)(grp*32)*HD + 4*q;
                #pragma unroll
                for (int j = 0; j < 32; j++) {
                    const float4 wv = *(const float4*)(Wb + (size_t)j*HD);
                    const float hv = hs[grp*32 + j];
                    a.x += hv*wv.x; a.y += hv*wv.y; a.z += hv*wv.z; a.w += hv*wv.w;
                }
                *(float4*)(part + grp*HD + 4*q) = a;
            }
            __syncthreads();
            const float xl = b_l[t] + part[t] + part[HD+t] + part[2*HD+t] + part[3*HD+t];

            if (!got) {   // xr0 only needed from here; producer overlapped
                if (t == 0) { while (g_xr0_flag == 0) {} }
                __syncthreads();
                __threadfence();
                myxr0 = g_xr0[t];
                got = true;
            }

            const float xs = xl + myxr0;
            const float lr = xs >= 0.f ? xs : 0.2f * xs;   // leaky_relu 0.2
            float v = lr * att[t];                          // att [4,128] row-major
            #pragma unroll
            for (int off = 16; off; off >>= 1)
                v += __shfl_xor_sync(0xffffffffu, v, off);
            if (lane == 0) red[warp] = v;
            __syncthreads();

            if (t < HEADS) {
                // softmax shift dropped (shift-invariant; logits O(1))
                float p = __expf(red[4*t] + red[4*t+1] + red[4*t+2] + red[4*t+3]);
                psh[t] = p;
                accD += p;
            }
            __syncthreads();
            accN += psh[t >> 7] * xl;
            __syncthreads();   // protect red/psh/part reuse
        }

        // single publish per block
        atomicAdd(&g_num[t], accN);
        if (t < HEADS) atomicAdd(&g_den[t], accD);
        __threadfence();
    }
    __syncthreads();
    if (t == 0) atomicAdd(&g_scanned, 1);
    // exit immediately — finale block owns the rest
}

extern "C" void kernel_launch(void* const* d_in, const int* in_sizes, int n_in,
                              void* d_out, int out_size) {
    const float* nf       = (const float*)d_in[0];
    const float* hidden   = (const float*)d_in[1];
    const float* W_enc    = (const float*)d_in[2];
    const float* b_enc    = (const float*)d_in[3];
    const float* W_l      = (const float*)d_in[4];
    const float* b_l      = (const float*)d_in[5];
    const float* W_r      = (const float*)d_in[6];
    const float* b_r      = (const float*)d_in[7];
    const float* att      = (const float*)d_in[8];
    const float* gat_bias = (const float*)d_in[9];
    const float* W_ih     = (const float*)d_in[10];
    const float* W_hh     = (const float*)d_in[11];
    const float* b_ih     = (const float*)d_in[12];
    const float* b_hh     = (const float*)d_in[13];
    const int*   ei       = (const int*)d_in[14];
    float* out = (float*)d_out;

    int E = in_sizes[14] / 2;

    fused_stgat<<<NBLK, NTHR>>>(nf, hidden, W_enc, b_enc, W_l, b_l, W_r, b_r,
                                att, gat_bias, W_ih, W_hh, b_ih, b_hh, ei, E, out);
}